// round 12
// baseline (speedup 1.0000x reference)
#include <cuda_runtime.h>
#include <cuda_bf16.h>
#include <cstdint>
#include <math.h>

#define BB 2
#define LL 1024
#define DM 768
#define NS 16
#define KC 4
#define DR 48
#define ML (BB*LL)          // 2048 rows
#define XPW (DR + 2*NS)     // 80
#define XSPL 6              // split-K factor for gemm_x

// ---------------- scratch (device globals; allocation forbidden) ----------
__device__ float g_xs0[ML*DM];
__device__ float g_sres[ML*DM];
__device__ float g_u[ML*DM];
__device__ float g_deltaT[ML*DM];     // (b,d,t)
__device__ float g_duT[ML*DM];        // (b,d,t) delta*u
__device__ float g_yT[ML*DM];         // (b,d,t) scan out
__device__ float g_bcT[BB*2*NS*LL];   // (b, ch, t): ch 0..15 = B, 16..31 = C
__device__ float g_xpp[XSPL*ML*XPW];  // split-K partials for gemm_x

// bf16 hi/lo operands for HMMA GEMMs
__device__ __nv_bfloat16 g_xhi[ML*DM],  g_xlo[ML*DM];       // x split  [M][768]
__device__ __nv_bfloat16 g_uhi[ML*DM],  g_ulo[ML*DM];       // u split  [M][768]
__device__ __nv_bfloat16 g_yhi[ML*DM],  g_ylo[ML*DM];       // y split  [M][768]
__device__ __nv_bfloat16 g_xphi[ML*64], g_xplo[ML*64];      // xp[:, :48] split (cols 48..63 stay 0)
__device__ __nv_bfloat16 g_wihi[2*DM*DM], g_wilo[2*DM*DM];  // W_in^T  [1536][768]
__device__ __nv_bfloat16 g_wohi[DM*DM],   g_wolo[DM*DM];    // W_out^T [768][768]
__device__ __nv_bfloat16 g_wxhi[XPW*DM],  g_wxlo[XPW*DM];   // W_x^T   [80][768]
__device__ __nv_bfloat16 g_wdhi[DM*64],   g_wdlo[DM*64];    // W_delta^T [768][64] (cols 48..63 stay 0)

__device__ __forceinline__ float silu_f(float x) {
    return x / (1.0f + __expf(-x));
}
__device__ __forceinline__ uint32_t smem_u32(const void* p) {
    uint32_t a;
    asm("{ .reg .u64 t; cvta.to.shared.u64 t, %1; cvt.u32.u64 %0, t; }" : "=r"(a) : "l"(p));
    return a;
}
#define CP16(dst, src) \
    asm volatile("cp.async.cg.shared.global [%0], [%1], 16;" :: "r"(dst), "l"(src) : "memory")
#define CP_COMMIT() asm volatile("cp.async.commit_group;" ::: "memory")
#define CP_WAIT1()  asm volatile("cp.async.wait_group 1;" ::: "memory")
#define CP_WAIT0()  asm volatile("cp.async.wait_group 0;" ::: "memory")

__device__ __forceinline__ void ldm_x4(uint32_t* r, uint32_t addr) {
    asm volatile("ldmatrix.sync.aligned.m8n8.x4.shared.b16 {%0,%1,%2,%3}, [%4];"
                 : "=r"(r[0]), "=r"(r[1]), "=r"(r[2]), "=r"(r[3]) : "r"(addr));
}
__device__ __forceinline__ void mma16816(float* c, const uint32_t* a, const uint32_t* b) {
    asm volatile(
        "mma.sync.aligned.m16n8k16.row.col.f32.bf16.bf16.f32 "
        "{%0,%1,%2,%3}, {%4,%5,%6,%7}, {%8,%9}, {%0,%1,%2,%3};"
        : "+f"(c[0]), "+f"(c[1]), "+f"(c[2]), "+f"(c[3])
        : "r"(a[0]), "r"(a[1]), "r"(a[2]), "r"(a[3]), "r"(b[0]), "r"(b[1]));
}
__device__ __forceinline__ void split_bf16(float x, __nv_bfloat16& h, __nv_bfloat16& l) {
    h = __float2bfloat16(x);
    l = __float2bfloat16(x - __bfloat162float(h));
}

// ---------------------------------------------------------------------------
// HMMA GEMM (bf16 two-term split, 3 product terms): C = A * B^T
//   CTA tile 128 x (NA*32) x BK32, 8 warps (2m x 4n), warp tile 64 x (NA*8),
//   2-stage cp.async pipeline. NA=2: 3 CTAs/SM. NA=4: 2 CTAs/SM (wide gemm1).
//   EPI 0: plain. EPI 1: gemm1 split (NA=4).
//   EPI 2: softplus/clip + fused transpose -> deltaT, duT. EPI 4: split-K.
// ---------------------------------------------------------------------------
#define HG_STRIDE 40                   // bf16 per smem row (32 data + 8 pad)
#define HG_TA (128*HG_STRIDE*2)        // 10240 B

template<int EPI, int NA>
__global__ __launch_bounds__(256, (NA == 4 ? 2 : 3))
void hgemm(const __nv_bfloat16* __restrict__ Ahi, const __nv_bfloat16* __restrict__ Alo,
           const __nv_bfloat16* __restrict__ Bhi, const __nv_bfloat16* __restrict__ Blo,
           float* __restrict__ C, const float* __restrict__ bias, int N, int K,
           int ksplit) {
    constexpr int BN = NA * 32;                    // CTA N-tile
    constexpr int TB = BN * HG_STRIDE * 2;         // B tile bytes (one of hi/lo)
    constexpr int STAGE = 2 * HG_TA + 2 * TB;

    extern __shared__ char hsm[];
    const uint32_t sb = smem_u32(hsm);
    const int tid = threadIdx.x;
    const int lane = tid & 31, wid = tid >> 5;
    const int wm = wid >> 2, wn = wid & 3;         // 2 (m) x 4 (n)
    const int bm = blockIdx.x * 128, bn = blockIdx.y * BN;

    int kcnt = K;
    if (EPI == 4) {
        kcnt = ksplit;
        const int ko = blockIdx.z * ksplit;
        Ahi += ko; Alo += ko; Bhi += ko; Blo += ko;
        C += (size_t)blockIdx.z * ML * N;
    }

    float acc[4][NA][4];
#pragma unroll
    for (int i = 0; i < 4; i++)
#pragma unroll
        for (int j = 0; j < NA; j++)
#pragma unroll
            for (int q = 0; q < 4; q++) acc[i][j][q] = 0.f;

    const int lr = tid >> 2;       // 0..63
    const int lc = (tid & 3) * 8;  // 0,8,16,24

    auto issue = [&](int c, int s) {
        const int k0 = c * 32;
        const uint32_t st = sb + s * STAGE;
#pragma unroll
        for (int h = 0; h < 2; h++) {
            const int row = lr + h * 64;
            const uint32_t so = (uint32_t)(row * HG_STRIDE + lc) * 2;
            const size_t ga = (size_t)(bm + row) * K + k0 + lc;
            CP16(st + so, Ahi + ga);
            CP16(st + HG_TA + so, Alo + ga);
        }
#pragma unroll
        for (int r = lr; r < BN; r += 64) {
            const uint32_t so = (uint32_t)(r * HG_STRIDE + lc) * 2;
            if (bn + r < N) {
                const size_t gb = (size_t)(bn + r) * K + k0 + lc;
                CP16(st + 2 * HG_TA + so, Bhi + gb);
                CP16(st + 2 * HG_TA + TB + so, Blo + gb);
            } else {
                *(uint4*)(hsm + s * STAGE + 2 * HG_TA + so) = make_uint4(0, 0, 0, 0);
                *(uint4*)(hsm + s * STAGE + 2 * HG_TA + TB + so) = make_uint4(0, 0, 0, 0);
            }
        }
    };

    const int nch = kcnt / 32;
    issue(0, 0);
    CP_COMMIT();

    const int a_r = lane & 15;
    const int a_k = (lane >> 4) * 8;
    const int b_row = ((lane >> 4) & 1) * 8 + (lane & 7);
    const int b_kk = ((lane >> 3) & 1) * 8;

    for (int c = 0; c < nch; c++) {
        if (c + 1 < nch) {
            issue(c + 1, (c + 1) & 1);
            CP_COMMIT();
            CP_WAIT1();            // group c complete; c+1 still in flight
        } else {
            CP_WAIT0();
        }
        __syncthreads();

        const uint32_t st = sb + (c & 1) * STAGE;
#pragma unroll
        for (int ks = 0; ks < 32; ks += 16) {
            // B frags FIRST (first MMA depends on them). 2*NA regs per hi/lo.
            uint32_t bh[2 * NA], bl[2 * NA];
#pragma unroll
            for (int g = 0; g < NA / 2; g++) {
                const uint32_t off =
                    (uint32_t)((wn * (NA * 8) + g * 16 + b_row) * HG_STRIDE + ks + b_kk) * 2;
                ldm_x4(bh + g * 4, st + 2 * HG_TA + off);
                ldm_x4(bl + g * 4, st + 2 * HG_TA + TB + off);
            }
            // per-ma: load frags then immediately use; ma+1 LDSM overlaps ma MMAs
#pragma unroll
            for (int ma = 0; ma < 4; ma++) {
                const uint32_t off =
                    (uint32_t)((wm * 64 + ma * 16 + a_r) * HG_STRIDE + ks + a_k) * 2;
                uint32_t ah[4], al[4];
                ldm_x4(ah, st + off);
                ldm_x4(al, st + HG_TA + off);
#pragma unroll
                for (int na = 0; na < NA; na++) mma16816(acc[ma][na], ah, bh + na * 2);
#pragma unroll
                for (int na = 0; na < NA; na++) mma16816(acc[ma][na], ah, bl + na * 2);
#pragma unroll
                for (int na = 0; na < NA; na++) mma16816(acc[ma][na], al, bh + na * 2);
            }
        }
        __syncthreads();           // stage reusable for issue(c+2)
    }

    // epilogue
    const int eg = lane >> 2, ei = lane & 3;
#pragma unroll
    for (int ma = 0; ma < 4; ma++) {
#pragma unroll
        for (int na = 0; na < NA; na++) {
            const int col = bn + wn * (NA * 8) + na * 8 + ei * 2;
#pragma unroll
            for (int h = 0; h < 2; h++) {
                const int row = bm + wm * 64 + ma * 16 + eg + h * 8;
                const float v0 = acc[ma][na][h * 2 + 0];
                const float v1 = acc[ma][na][h * 2 + 1];
                if (EPI == 0) {
                    *(float2*)(&C[(size_t)row * N + col]) = make_float2(v0, v1);
                } else if (EPI == 1) {
                    if (col < DM)
                        *(float2*)(&g_xs0[(size_t)row * DM + col]) = make_float2(v0, v1);
                    else
                        *(float2*)(&g_sres[(size_t)row * DM + (col - DM)]) =
                            make_float2(silu_f(v0), silu_f(v1));
                } else if (EPI == 2) {
                    // delta: bias + softplus + clip, then fused transpose
                    const int b = row / LL, t = row - b * LL;
                    const float2 uu = *(const float2*)(&g_u[(size_t)row * DM + col]);
#pragma unroll
                    for (int q = 0; q < 2; q++) {
                        float v = (q ? v1 : v0) + bias[col + q];
                        float sp = (v > 0.f) ? (v + log1pf(__expf(-v))) : log1pf(__expf(v));
                        sp = fminf(fmaxf(sp, 1e-4f), 0.1f);
                        const size_t o = ((size_t)b * DM + col + q) * LL + t;
                        g_deltaT[o] = sp;
                        g_duT[o] = sp * (q ? uu.y : uu.x);
                    }
                } else {   // EPI 4: split-K partial, cols guarded by N
                    if (col + 1 < N)
                        *(float2*)(&C[(size_t)row * N + col]) = make_float2(v0, v1);
                    else if (col < N)
                        C[(size_t)row * N + col] = v0;
                }
            }
        }
    }
}

#define HG_SMEM_N2 (2*(2*HG_TA + 2*(64*HG_STRIDE*2)))    // 61440
#define HG_SMEM_N4 (2*(2*HG_TA + 2*(128*HG_STRIDE*2)))   // 81920

// ---------------------------------------------------------------------------
// Split-K reduce for gemm_x
// ---------------------------------------------------------------------------
__global__ __launch_bounds__(256)
void reduce_xp_kernel() {
    const int idx = blockIdx.x * blockDim.x + threadIdx.x;   // < ML*XPW
    float s = 0.f;
#pragma unroll
    for (int z = 0; z < XSPL; z++) s += g_xpp[(size_t)z * ML * XPW + idx];
    const int cc = idx % XPW;
    const int row = idx / XPW;
    if (cc < DR) {
        __nv_bfloat16 hh, ll;
        split_bf16(s, hh, ll);
        g_xphi[(size_t)row * 64 + cc] = hh;
        g_xplo[(size_t)row * 64 + cc] = ll;
    } else {
        const int b = row / LL, t = row % LL;
        g_bcT[((size_t)b * 2 * NS + (cc - DR)) * LL + t] = s;
    }
}

// ---------------------------------------------------------------------------
// Fused prep: x split + all 4 weight transposes in one launch.
// ---------------------------------------------------------------------------
__device__ __forceinline__ void wtrans_tile(const float* __restrict__ W,
                                            __nv_bfloat16* __restrict__ Whi,
                                            __nv_bfloat16* __restrict__ Wlo,
                                            int Kdim, int Ndim, int ldout,
                                            int kb, int nb) {
    __shared__ float tl[32][33];
    const int k0 = kb * 32, n0 = nb * 32;
    const int tx = threadIdx.x & 31, ty = threadIdx.x >> 5;
#pragma unroll
    for (int j = 0; j < 4; j++) {
        int k = k0 + ty + j * 8;
        int n = n0 + tx;
        tl[ty + j * 8][tx] = (k < Kdim && n < Ndim) ? W[(size_t)k * Ndim + n] : 0.f;
    }
    __syncthreads();
#pragma unroll
    for (int j = 0; j < 4; j++) {
        int n = n0 + ty + j * 8;
        int k = k0 + tx;
        if (n < Ndim && k < Kdim) {
            __nv_bfloat16 h, l;
            split_bf16(tl[tx][ty + j * 8], h, l);
            Whi[(size_t)n * ldout + k] = h;
            Wlo[(size_t)n * ldout + k] = l;
        }
    }
}

#define PREP_XBLK (ML*DM/1024)     // 1536
__global__ __launch_bounds__(256)
void prep_all_kernel(const float* __restrict__ x, const float* __restrict__ W_in,
                     const float* __restrict__ W_out, const float* __restrict__ W_x,
                     const float* __restrict__ W_delta) {
    int blk = blockIdx.x;
    if (blk < PREP_XBLK) {
        const int i4 = blk * 256 + threadIdx.x;
        float4 v = ((const float4*)x)[i4];
        __nv_bfloat16 h0, l0, h1, l1, h2, l2, h3, l3;
        split_bf16(v.x, h0, l0); split_bf16(v.y, h1, l1);
        split_bf16(v.z, h2, l2); split_bf16(v.w, h3, l3);
        __nv_bfloat162* ph = (__nv_bfloat162*)g_xhi;
        __nv_bfloat162* pl = (__nv_bfloat162*)g_xlo;
        ph[i4 * 2]     = __nv_bfloat162(h0, h1);
        ph[i4 * 2 + 1] = __nv_bfloat162(h2, h3);
        pl[i4 * 2]     = __nv_bfloat162(l0, l1);
        pl[i4 * 2 + 1] = __nv_bfloat162(l2, l3);
        return;
    }
    blk -= PREP_XBLK;
    if (blk < 1152) { wtrans_tile(W_in, g_wihi, g_wilo, DM, 2 * DM, DM, blk % 24, blk / 24); return; }
    blk -= 1152;
    if (blk < 576)  { wtrans_tile(W_out, g_wohi, g_wolo, DM, DM, DM, blk % 24, blk / 24); return; }
    blk -= 576;
    if (blk < 72)   { wtrans_tile(W_x, g_wxhi, g_wxlo, DM, XPW, DM, blk % 24, blk / 24); return; }
    blk -= 72;
    wtrans_tile(W_delta, g_wdhi, g_wdlo, DR, DM, 64, blk % 2, blk / 2);
}
#define PREP_BLKS (PREP_XBLK + 1152 + 576 + 72 + 48)

// ---------------------------------------------------------------------------
// Depthwise causal conv + bias + SiLU -> u (+ bf16 split)
// ---------------------------------------------------------------------------
__global__ __launch_bounds__(256)
void conv_silu_kernel(const float* __restrict__ conv_w, const float* __restrict__ conv_b) {
    int idx = blockIdx.x * blockDim.x + threadIdx.x;
    if (idx >= ML * DM) return;
    int d = idx % DM;
    int t = (idx / DM) % LL;
    int base = idx - t * DM - d;
    float acc = conv_b[d];
#pragma unroll
    for (int k = 0; k < KC; k++) {
        int tt = t - (KC - 1) + k;
        if (tt >= 0)
            acc = fmaf(conv_w[d * KC + k], g_xs0[base + tt * DM + d], acc);
    }
    float u = silu_f(acc);
    g_u[idx] = u;
    split_bf16(u, g_uhi[idx], g_ulo[idx]);
}

// ---------------------------------------------------------------------------
// Parallel selective scan. One block per (b,d).
// ---------------------------------------------------------------------------
__global__ __launch_bounds__(256)
void scan_par_kernel(const float* __restrict__ A_log) {
    __shared__ float pd[LL];
    __shared__ float du[LL];
    __shared__ float ysw[8][LL];
    __shared__ float wsum[9];
    const int bd = blockIdx.x;
    const int b = bd / DM, d = bd - b * DM;
    const int tid = threadIdx.x, lane = tid & 31, wrp = tid >> 5;
    const float* dT  = g_deltaT + (size_t)bd * LL;
    const float* duT = g_duT    + (size_t)bd * LL;

    float4 v = ((const float4*)dT)[tid];
    ((float4*)du)[tid] = ((const float4*)duT)[tid];
    float s0 = v.x, s1 = s0 + v.y, s2 = s1 + v.z, s3 = s2 + v.w;
    float ts = s3;
#pragma unroll
    for (int o = 1; o < 32; o <<= 1) {
        float nv = __shfl_up_sync(0xffffffffu, ts, o);
        if (lane >= o) ts += nv;
    }
    if (lane == 31) wsum[wrp] = ts;
    __syncthreads();
    if (tid == 0) {
        float a = 0.f;
#pragma unroll
        for (int i = 0; i < 8; i++) { float x = wsum[i]; wsum[i] = a; a += x; }
        wsum[8] = a;
    }
    __syncthreads();
    float base = wsum[wrp] + ts - s3;
    pd[tid * 4 + 0] = base + s0;
    pd[tid * 4 + 1] = base + s1;
    pd[tid * 4 + 2] = base + s2;
    pd[tid * 4 + 3] = base + s3;
    const float S = wsum[8];
    __syncthreads();

    const int n0 = wrp, n1 = wrp + 8;
    const float An0 = -__expf(A_log[d * NS + n0]);
    const float An1 = -__expf(A_log[d * NS + n1]);
    const float* B0p = g_bcT + ((size_t)b * 2 * NS + n0) * LL;
    const float* C0p = g_bcT + ((size_t)b * 2 * NS + NS + n0) * LL;
    const float* B1p = g_bcT + ((size_t)b * 2 * NS + n1) * LL;
    const float* C1p = g_bcT + ((size_t)b * 2 * NS + NS + n1) * LL;
    float carry0 = 0.f, carry1 = 0.f;

#pragma unroll
    for (int j = 0; j < 8; j++) {
        const int t = j * 128 + lane * 4;
        float dv[4], pv[4], b0[4], c0[4], b1[4], c1[4];
        *(float4*)dv = *(const float4*)&du[t];
        *(float4*)pv = *(const float4*)&pd[t];
        *(float4*)b0 = *(const float4*)&B0p[t];
        *(float4*)c0 = *(const float4*)&C0p[t];
        *(float4*)b1 = *(const float4*)&B1p[t];
        *(float4*)c1 = *(const float4*)&C1p[t];

        float e0[4], e1[4], p0[4], p1[4];
#pragma unroll
        for (int q = 0; q < 4; q++) {
            e0[q] = __expf(An0 * (S - pv[q]));
            e1[q] = __expf(An1 * (S - pv[q]));
            float z0 = dv[q] * b0[q] * e0[q];
            float z1 = dv[q] * b1[q] * e1[q];
            p0[q] = q ? (p0[q - 1] + z0) : z0;
            p1[q] = q ? (p1[q - 1] + z1) : z1;
        }
        float t0 = p0[3], t1 = p1[3];
#pragma unroll
        for (int o = 1; o < 32; o <<= 1) {
            float a0 = __shfl_up_sync(0xffffffffu, t0, o);
            float a1 = __shfl_up_sync(0xffffffffu, t1, o);
            if (lane >= o) { t0 += a0; t1 += a1; }
        }
        const float bs0 = carry0 + t0 - p0[3];
        const float bs1 = carry1 + t1 - p1[3];
        carry0 += __shfl_sync(0xffffffffu, t0, 31);
        carry1 += __shfl_sync(0xffffffffu, t1, 31);

        float acc4[4];
#pragma unroll
        for (int q = 0; q < 4; q++) {
            float x0 = (bs0 + p0[q]) / (e0[q] + 1e-12f);
            float x1 = (bs1 + p1[q]) / (e1[q] + 1e-12f);
            acc4[q] = x0 * c0[q] + x1 * c1[q];
        }
        *(float4*)&ysw[wrp][t] = *(const float4*)acc4;
    }
    __syncthreads();

    float4 r = ((const float4*)ysw[0])[tid];
#pragma unroll
    for (int w = 1; w < 8; w++) {
        float4 q = ((const float4*)ysw[w])[tid];
        r.x += q.x; r.y += q.y; r.z += q.z; r.w += q.w;
    }
    ((float4*)(g_yT + (size_t)bd * LL))[tid] = r;
}

// ---------------------------------------------------------------------------
// Transpose back + gate + bf16 split of y
// ---------------------------------------------------------------------------
__global__ __launch_bounds__(256)
void back_gate_kernel(const float* __restrict__ D_param) {
    __shared__ float tl[32][33];
    const int r0 = blockIdx.x * 32, d0 = blockIdx.y * 32;
    const int b = r0 / LL, tb = r0 % LL;
#pragma unroll
    for (int j = 0; j < 4; j++) {
        int d = d0 + threadIdx.y + j * 8;
        tl[threadIdx.y + j * 8][threadIdx.x] =
            g_yT[((size_t)b * DM + d) * LL + tb + threadIdx.x];
    }
    __syncthreads();
#pragma unroll
    for (int j = 0; j < 4; j++) {
        int row = r0 + threadIdx.y + j * 8;
        int d = d0 + threadIdx.x;
        float v = tl[threadIdx.x][threadIdx.y + j * 8];
        float uu = g_u[(size_t)row * DM + d];
        float sr = g_sres[(size_t)row * DM + d];
        float y = (v + uu * D_param[d]) * sr;
        __nv_bfloat16 h, l;
        split_bf16(y, h, l);
        g_yhi[(size_t)row * DM + d] = h;
        g_ylo[(size_t)row * DM + d] = l;
    }
}

// ---------------------------------------------------------------------------
extern "C" void kernel_launch(void* const* d_in, const int* in_sizes, int n_in,
                              void* d_out, int out_size) {
    const float* x       = (const float*)d_in[0];
    const float* W_in    = (const float*)d_in[1];
    const float* conv_w  = (const float*)d_in[2];
    const float* conv_b  = (const float*)d_in[3];
    const float* W_x     = (const float*)d_in[4];
    const float* W_delta = (const float*)d_in[5];
    const float* b_delta = (const float*)d_in[6];
    const float* A_log   = (const float*)d_in[7];
    const float* D_param = (const float*)d_in[8];
    const float* W_out   = (const float*)d_in[9];
    float* out = (float*)d_out;

    cudaFuncSetAttribute((const void*)hgemm<0, 2>, cudaFuncAttributeMaxDynamicSharedMemorySize, HG_SMEM_N2);
    cudaFuncSetAttribute((const void*)hgemm<1, 4>, cudaFuncAttributeMaxDynamicSharedMemorySize, HG_SMEM_N4);
    cudaFuncSetAttribute((const void*)hgemm<2, 2>, cudaFuncAttributeMaxDynamicSharedMemorySize, HG_SMEM_N2);
    cudaFuncSetAttribute((const void*)hgemm<4, 2>, cudaFuncAttributeMaxDynamicSharedMemorySize, HG_SMEM_N2);

    float* p_xpp;
    cudaGetSymbolAddress((void**)&p_xpp, g_xpp);
    __nv_bfloat16 *p_xhi, *p_xlo, *p_uhi, *p_ulo, *p_yhi, *p_ylo, *p_xphi, *p_xplo;
    __nv_bfloat16 *p_wihi, *p_wilo, *p_wohi, *p_wolo, *p_wxhi, *p_wxlo, *p_wdhi, *p_wdlo;
    cudaGetSymbolAddress((void**)&p_xhi, g_xhi);
    cudaGetSymbolAddress((void**)&p_xlo, g_xlo);
    cudaGetSymbolAddress((void**)&p_uhi, g_uhi);
    cudaGetSymbolAddress((void**)&p_ulo, g_ulo);
    cudaGetSymbolAddress((void**)&p_yhi, g_yhi);
    cudaGetSymbolAddress((void**)&p_ylo, g_ylo);
    cudaGetSymbolAddress((void**)&p_xphi, g_xphi);
    cudaGetSymbolAddress((void**)&p_xplo, g_xplo);
    cudaGetSymbolAddress((void**)&p_wihi, g_wihi);
    cudaGetSymbolAddress((void**)&p_wilo, g_wilo);
    cudaGetSymbolAddress((void**)&p_wohi, g_wohi);
    cudaGetSymbolAddress((void**)&p_wolo, g_wolo);
    cudaGetSymbolAddress((void**)&p_wxhi, g_wxhi);
    cudaGetSymbolAddress((void**)&p_wxlo, g_wxlo);
    cudaGetSymbolAddress((void**)&p_wdhi, g_wdhi);
    cudaGetSymbolAddress((void**)&p_wdlo, g_wdlo);

    // 0) all prep in one launch
    prep_all_kernel<<<PREP_BLKS, 256>>>(x, W_in, W_out, W_x, W_delta);
    // 1) gemm1 (wide NA=4): x @ W_in -> xs0 | silu(res); grid 16x12=192
    hgemm<1, 4><<<dim3(ML / 128, (2 * DM) / 128), 256, HG_SMEM_N4>>>(
        p_xhi, p_xlo, p_wihi, p_wilo, nullptr, nullptr, 2 * DM, DM, 0);
    // 2) conv + silu -> u (+ split)
    conv_silu_kernel<<<(ML * DM + 255) / 256, 256>>>(conv_w, conv_b);
    // 3) gemm_x split-K=6: u @ W_x -> partials
    hgemm<4, 2><<<dim3(ML / 128, 2, XSPL), 256, HG_SMEM_N2>>>(
        p_uhi, p_ulo, p_wxhi, p_wxlo, p_xpp, nullptr, XPW, DM, DM / XSPL);
    // 3b) reduce partials -> xphi/xplo + bcT
    reduce_xp_kernel<<<(ML * XPW) / 256, 256>>>();
    // 4) delta gemm (fused transpose epilogue -> deltaT, duT)
    hgemm<2, 2><<<dim3(ML / 128, DM / 64), 256, HG_SMEM_N2>>>(
        p_xphi, p_xplo, p_wdhi, p_wdlo, nullptr, b_delta, DM, 64, 0);
    // 5) scan, gate
    scan_par_kernel<<<BB * DM, 256>>>(A_log);
    back_gate_kernel<<<dim3(ML / 32, DM / 32), dim3(32, 8)>>>(D_param);
    // 6) out = y @ W_out
    hgemm<0, 2><<<dim3(ML / 128, DM / 64), 256, HG_SMEM_N2>>>(
        p_yhi, p_ylo, p_wohi, p_wolo, out, nullptr, DM, DM, 0);
}

// round 15
// speedup vs baseline: 1.0972x; 1.0972x over previous
#include <cuda_runtime.h>
#include <cuda_bf16.h>
#include <cstdint>
#include <math.h>

#define BB 2
#define LL 1024
#define DM 768
#define NS 16
#define KC 4
#define DR 48
#define ML (BB*LL)          // 2048 rows
#define XPW (DR + 2*NS)     // 80
#define XSPL 8              // split-K factor for gemm_x
#define OSPL 2              // split-K factor for gemm_out

// ---------------- scratch (device globals; allocation forbidden) ----------
__device__ float g_xs0[ML*DM];
__device__ float g_sres[ML*DM];
__device__ float g_u[ML*DM];
__device__ float g_deltaT[ML*DM];     // (b,d,t)
__device__ float g_duT[ML*DM];        // (b,d,t) delta*u
__device__ float g_yT[ML*DM];         // (b,d,t) scan out
__device__ float g_bcT[BB*2*NS*LL];   // (b, ch, t): ch 0..15 = B, 16..31 = C
__device__ float g_xpp[XSPL*ML*XPW];  // split-K partials for gemm_x
__device__ float g_pout[OSPL*ML*DM];  // split-K partials for gemm_out

// bf16 hi/lo operands for HMMA GEMMs
__device__ __nv_bfloat16 g_xhi[ML*DM],  g_xlo[ML*DM];       // x split  [M][768]
__device__ __nv_bfloat16 g_uhi[ML*DM],  g_ulo[ML*DM];       // u split  [M][768]
__device__ __nv_bfloat16 g_yhi[ML*DM],  g_ylo[ML*DM];       // y split  [M][768]
__device__ __nv_bfloat16 g_xphi[ML*64], g_xplo[ML*64];      // xp[:, :48] split (cols 48..63 stay 0)
__device__ __nv_bfloat16 g_wihi[2*DM*DM], g_wilo[2*DM*DM];  // W_in^T  [1536][768]
__device__ __nv_bfloat16 g_wohi[DM*DM],   g_wolo[DM*DM];    // W_out^T [768][768]
__device__ __nv_bfloat16 g_wxhi[XPW*DM],  g_wxlo[XPW*DM];   // W_x^T   [80][768]
__device__ __nv_bfloat16 g_wdhi[DM*64],   g_wdlo[DM*64];    // W_delta^T [768][64] (cols 48..63 stay 0)

__device__ __forceinline__ float silu_f(float x) {
    return x / (1.0f + __expf(-x));
}
__device__ __forceinline__ uint32_t smem_u32(const void* p) {
    uint32_t a;
    asm("{ .reg .u64 t; cvta.to.shared.u64 t, %1; cvt.u32.u64 %0, t; }" : "=r"(a) : "l"(p));
    return a;
}
#define CP16(dst, src) \
    asm volatile("cp.async.cg.shared.global [%0], [%1], 16;" :: "r"(dst), "l"(src) : "memory")
#define CP_COMMIT() asm volatile("cp.async.commit_group;" ::: "memory")
#define CP_WAIT1()  asm volatile("cp.async.wait_group 1;" ::: "memory")
#define CP_WAIT0()  asm volatile("cp.async.wait_group 0;" ::: "memory")

__device__ __forceinline__ void ldm_x4(uint32_t* r, uint32_t addr) {
    asm volatile("ldmatrix.sync.aligned.m8n8.x4.shared.b16 {%0,%1,%2,%3}, [%4];"
                 : "=r"(r[0]), "=r"(r[1]), "=r"(r[2]), "=r"(r[3]) : "r"(addr));
}
__device__ __forceinline__ void mma16816(float* c, const uint32_t* a, const uint32_t* b) {
    asm volatile(
        "mma.sync.aligned.m16n8k16.row.col.f32.bf16.bf16.f32 "
        "{%0,%1,%2,%3}, {%4,%5,%6,%7}, {%8,%9}, {%0,%1,%2,%3};"
        : "+f"(c[0]), "+f"(c[1]), "+f"(c[2]), "+f"(c[3])
        : "r"(a[0]), "r"(a[1]), "r"(a[2]), "r"(a[3]), "r"(b[0]), "r"(b[1]));
}
__device__ __forceinline__ void split_bf16(float x, __nv_bfloat16& h, __nv_bfloat16& l) {
    h = __float2bfloat16(x);
    l = __float2bfloat16(x - __bfloat162float(h));
}

// ---------------------------------------------------------------------------
// HMMA GEMM (bf16 two-term split, 3 product terms): C = A * B^T
//   CTA tile 128x64xBK32, 8 warps (2x4), 2-stage cp.async pipeline,
//   3 CTAs/SM (R8/R11-proven). Per-ma interleaved A-ldm + MMA.
//   EPI 0: plain. EPI 1: gemm1 split.
//   EPI 2: softplus/clip + fused transpose -> deltaT, duT.
//   EPI 4: split-K partial: C + (z*ML + row)*N + col, ksplit K per z.
// ---------------------------------------------------------------------------
#define HG_STRIDE 40                   // bf16 per smem row (32 data + 8 pad)
#define HG_TA (128*HG_STRIDE*2)        // 10240 B
#define HG_TB (64*HG_STRIDE*2)         // 5120 B
#define HG_STAGE (2*HG_TA + 2*HG_TB)   // 30720 B
#define HG_NSTG 2
#define HG_SMEM (HG_NSTG*HG_STAGE)     // 61440 B

template<int EPI>
__global__ __launch_bounds__(256, 3)
void hgemm(const __nv_bfloat16* __restrict__ Ahi, const __nv_bfloat16* __restrict__ Alo,
           const __nv_bfloat16* __restrict__ Bhi, const __nv_bfloat16* __restrict__ Blo,
           float* __restrict__ C, const float* __restrict__ bias, int N, int K,
           int ksplit) {
    extern __shared__ char hsm[];
    const uint32_t sb = smem_u32(hsm);
    const int tid = threadIdx.x;
    const int lane = tid & 31, wid = tid >> 5;
    const int wm = wid >> 2, wn = wid & 3;         // 2 (m) x 4 (n)
    const int bm = blockIdx.x * 128, bn = blockIdx.y * 64;

    int kcnt = K;
    if (EPI == 4) {
        kcnt = ksplit;
        const int ko = blockIdx.z * ksplit;
        Ahi += ko; Alo += ko; Bhi += ko; Blo += ko;
        C += (size_t)blockIdx.z * ML * N;
    }

    float acc[4][2][4];
#pragma unroll
    for (int i = 0; i < 4; i++)
#pragma unroll
        for (int j = 0; j < 2; j++)
#pragma unroll
            for (int q = 0; q < 4; q++) acc[i][j][q] = 0.f;

    const int lr = tid >> 2;       // 0..63
    const int lc = (tid & 3) * 8;  // 0,8,16,24
    const bool bvalid = (bn + lr) < N;

    auto issue = [&](int c, int s) {
        const int k0 = c * 32;
        const uint32_t st = sb + s * HG_STAGE;
#pragma unroll
        for (int h = 0; h < 2; h++) {
            const int row = lr + h * 64;
            const uint32_t so = (uint32_t)(row * HG_STRIDE + lc) * 2;
            const size_t ga = (size_t)(bm + row) * K + k0 + lc;
            CP16(st + so, Ahi + ga);
            CP16(st + HG_TA + so, Alo + ga);
        }
        const uint32_t so = (uint32_t)(lr * HG_STRIDE + lc) * 2;
        if (bvalid) {
            const size_t gb = (size_t)(bn + lr) * K + k0 + lc;
            CP16(st + 2 * HG_TA + so, Bhi + gb);
            CP16(st + 2 * HG_TA + HG_TB + so, Blo + gb);
        } else {
            *(uint4*)(hsm + s * HG_STAGE + 2 * HG_TA + so) = make_uint4(0, 0, 0, 0);
            *(uint4*)(hsm + s * HG_STAGE + 2 * HG_TA + HG_TB + so) = make_uint4(0, 0, 0, 0);
        }
    };

    const int nch = kcnt / 32;
    issue(0, 0);
    CP_COMMIT();

    const int a_r = lane & 15;
    const int a_k = (lane >> 4) * 8;
    const int b_row = ((lane >> 4) & 1) * 8 + (lane & 7);
    const int b_kk = ((lane >> 3) & 1) * 8;

    for (int c = 0; c < nch; c++) {
        if (c + 1 < nch) {
            issue(c + 1, (c + 1) & 1);
            CP_COMMIT();
            CP_WAIT1();            // group c complete; c+1 still in flight
        } else {
            CP_WAIT0();
        }
        __syncthreads();

        const uint32_t st = sb + (c & 1) * HG_STAGE;
#pragma unroll
        for (int ks = 0; ks < 32; ks += 16) {
            // B frags FIRST (first MMA depends on them)
            uint32_t bh[4], bl[4];
            {
                const uint32_t off =
                    (uint32_t)((wn * 16 + b_row) * HG_STRIDE + ks + b_kk) * 2;
                ldm_x4(bh, st + 2 * HG_TA + off);
                ldm_x4(bl, st + 2 * HG_TA + HG_TB + off);
            }
            // per-ma: load frags then immediately use; ma+1 LDSM overlaps ma MMAs
#pragma unroll
            for (int ma = 0; ma < 4; ma++) {
                const uint32_t off =
                    (uint32_t)((wm * 64 + ma * 16 + a_r) * HG_STRIDE + ks + a_k) * 2;
                uint32_t ah[4], al[4];
                ldm_x4(ah, st + off);
                ldm_x4(al, st + HG_TA + off);
                mma16816(acc[ma][0], ah, bh);
                mma16816(acc[ma][1], ah, bh + 2);
                mma16816(acc[ma][0], ah, bl);
                mma16816(acc[ma][1], ah, bl + 2);
                mma16816(acc[ma][0], al, bh);
                mma16816(acc[ma][1], al, bh + 2);
            }
        }
        __syncthreads();           // stage reusable for issue(c+2)
    }

    // epilogue
    const int eg = lane >> 2, ei = lane & 3;
#pragma unroll
    for (int ma = 0; ma < 4; ma++) {
#pragma unroll
        for (int na = 0; na < 2; na++) {
            const int col = bn + wn * 16 + na * 8 + ei * 2;
#pragma unroll
            for (int h = 0; h < 2; h++) {
                const int row = bm + wm * 64 + ma * 16 + eg + h * 8;
                const float v0 = acc[ma][na][h * 2 + 0];
                const float v1 = acc[ma][na][h * 2 + 1];
                if (EPI == 0) {
                    *(float2*)(&C[(size_t)row * N + col]) = make_float2(v0, v1);
                } else if (EPI == 1) {
                    if (col < DM)
                        *(float2*)(&g_xs0[(size_t)row * DM + col]) = make_float2(v0, v1);
                    else
                        *(float2*)(&g_sres[(size_t)row * DM + (col - DM)]) =
                            make_float2(silu_f(v0), silu_f(v1));
                } else if (EPI == 2) {
                    // delta: bias + softplus + clip, then fused transpose
                    const int b = row / LL, t = row - b * LL;
                    const float2 uu = *(const float2*)(&g_u[(size_t)row * DM + col]);
#pragma unroll
                    for (int q = 0; q < 2; q++) {
                        float v = (q ? v1 : v0) + bias[col + q];
                        float sp = (v > 0.f) ? (v + log1pf(__expf(-v))) : log1pf(__expf(v));
                        sp = fminf(fmaxf(sp, 1e-4f), 0.1f);
                        const size_t o = ((size_t)b * DM + col + q) * LL + t;
                        g_deltaT[o] = sp;
                        g_duT[o] = sp * (q ? uu.y : uu.x);
                    }
                } else {   // EPI 4: split-K partial, cols guarded by N
                    if (col + 1 < N)
                        *(float2*)(&C[(size_t)row * N + col]) = make_float2(v0, v1);
                    else if (col < N)
                        C[(size_t)row * N + col] = v0;
                }
            }
        }
    }
}

// ---------------------------------------------------------------------------
// Split-K reduce for gemm_x
// ---------------------------------------------------------------------------
__global__ __launch_bounds__(256)
void reduce_xp_kernel() {
    const int idx = blockIdx.x * blockDim.x + threadIdx.x;   // < ML*XPW
    float s = 0.f;
#pragma unroll
    for (int z = 0; z < XSPL; z++) s += g_xpp[(size_t)z * ML * XPW + idx];
    const int cc = idx % XPW;
    const int row = idx / XPW;
    if (cc < DR) {
        __nv_bfloat16 hh, ll;
        split_bf16(s, hh, ll);
        g_xphi[(size_t)row * 64 + cc] = hh;
        g_xplo[(size_t)row * 64 + cc] = ll;
    } else {
        const int b = row / LL, t = row % LL;
        g_bcT[((size_t)b * 2 * NS + (cc - DR)) * LL + t] = s;
    }
}

// ---------------------------------------------------------------------------
// Split-K reduce for gemm_out: out = p0 + p1 (float4)
// ---------------------------------------------------------------------------
__global__ __launch_bounds__(256)
void reduce_out_kernel(float* __restrict__ out) {
    const int i4 = blockIdx.x * blockDim.x + threadIdx.x;    // < ML*DM/4
    const float4 a = ((const float4*)g_pout)[i4];
    const float4 b = ((const float4*)(g_pout + (size_t)ML * DM))[i4];
    ((float4*)out)[i4] = make_float4(a.x + b.x, a.y + b.y, a.z + b.z, a.w + b.w);
}

// ---------------------------------------------------------------------------
// Fused prep: x split + all 4 weight transposes in one launch.
// ---------------------------------------------------------------------------
__device__ __forceinline__ void wtrans_tile(const float* __restrict__ W,
                                            __nv_bfloat16* __restrict__ Whi,
                                            __nv_bfloat16* __restrict__ Wlo,
                                            int Kdim, int Ndim, int ldout,
                                            int kb, int nb) {
    __shared__ float tl[32][33];
    const int k0 = kb * 32, n0 = nb * 32;
    const int tx = threadIdx.x & 31, ty = threadIdx.x >> 5;
#pragma unroll
    for (int j = 0; j < 4; j++) {
        int k = k0 + ty + j * 8;
        int n = n0 + tx;
        tl[ty + j * 8][tx] = (k < Kdim && n < Ndim) ? W[(size_t)k * Ndim + n] : 0.f;
    }
    __syncthreads();
#pragma unroll
    for (int j = 0; j < 4; j++) {
        int n = n0 + ty + j * 8;
        int k = k0 + tx;
        if (n < Ndim && k < Kdim) {
            __nv_bfloat16 h, l;
            split_bf16(tl[tx][ty + j * 8], h, l);
            Whi[(size_t)n * ldout + k] = h;
            Wlo[(size_t)n * ldout + k] = l;
        }
    }
}

#define PREP_XBLK (ML*DM/1024)     // 1536
__global__ __launch_bounds__(256)
void prep_all_kernel(const float* __restrict__ x, const float* __restrict__ W_in,
                     const float* __restrict__ W_out, const float* __restrict__ W_x,
                     const float* __restrict__ W_delta) {
    int blk = blockIdx.x;
    if (blk < PREP_XBLK) {
        const int i4 = blk * 256 + threadIdx.x;
        float4 v = ((const float4*)x)[i4];
        __nv_bfloat16 h0, l0, h1, l1, h2, l2, h3, l3;
        split_bf16(v.x, h0, l0); split_bf16(v.y, h1, l1);
        split_bf16(v.z, h2, l2); split_bf16(v.w, h3, l3);
        __nv_bfloat162* ph = (__nv_bfloat162*)g_xhi;
        __nv_bfloat162* pl = (__nv_bfloat162*)g_xlo;
        ph[i4 * 2]     = __nv_bfloat162(h0, h1);
        ph[i4 * 2 + 1] = __nv_bfloat162(h2, h3);
        pl[i4 * 2]     = __nv_bfloat162(l0, l1);
        pl[i4 * 2 + 1] = __nv_bfloat162(l2, l3);
        return;
    }
    blk -= PREP_XBLK;
    if (blk < 1152) { wtrans_tile(W_in, g_wihi, g_wilo, DM, 2 * DM, DM, blk % 24, blk / 24); return; }
    blk -= 1152;
    if (blk < 576)  { wtrans_tile(W_out, g_wohi, g_wolo, DM, DM, DM, blk % 24, blk / 24); return; }
    blk -= 576;
    if (blk < 72)   { wtrans_tile(W_x, g_wxhi, g_wxlo, DM, XPW, DM, blk % 24, blk / 24); return; }
    blk -= 72;
    wtrans_tile(W_delta, g_wdhi, g_wdlo, DR, DM, 64, blk % 2, blk / 2);
}
#define PREP_BLKS (PREP_XBLK + 1152 + 576 + 72 + 48)

// ---------------------------------------------------------------------------
// Depthwise causal conv + bias + SiLU -> u (+ bf16 split)
// ---------------------------------------------------------------------------
__global__ __launch_bounds__(256)
void conv_silu_kernel(const float* __restrict__ conv_w, const float* __restrict__ conv_b) {
    int idx = blockIdx.x * blockDim.x + threadIdx.x;
    if (idx >= ML * DM) return;
    int d = idx % DM;
    int t = (idx / DM) % LL;
    int base = idx - t * DM - d;
    float acc = conv_b[d];
#pragma unroll
    for (int k = 0; k < KC; k++) {
        int tt = t - (KC - 1) + k;
        if (tt >= 0)
            acc = fmaf(conv_w[d * KC + k], g_xs0[base + tt * DM + d], acc);
    }
    float u = silu_f(acc);
    g_u[idx] = u;
    split_bf16(u, g_uhi[idx], g_ulo[idx]);
}

// ---------------------------------------------------------------------------
// Parallel selective scan. One block per (b,d).
// ---------------------------------------------------------------------------
__global__ __launch_bounds__(256)
void scan_par_kernel(const float* __restrict__ A_log) {
    __shared__ float pd[LL];
    __shared__ float du[LL];
    __shared__ float ysw[8][LL];
    __shared__ float wsum[9];
    const int bd = blockIdx.x;
    const int b = bd / DM, d = bd - b * DM;
    const int tid = threadIdx.x, lane = tid & 31, wrp = tid >> 5;
    const float* dT  = g_deltaT + (size_t)bd * LL;
    const float* duT = g_duT    + (size_t)bd * LL;

    float4 v = ((const float4*)dT)[tid];
    ((float4*)du)[tid] = ((const float4*)duT)[tid];
    float s0 = v.x, s1 = s0 + v.y, s2 = s1 + v.z, s3 = s2 + v.w;
    float ts = s3;
#pragma unroll
    for (int o = 1; o < 32; o <<= 1) {
        float nv = __shfl_up_sync(0xffffffffu, ts, o);
        if (lane >= o) ts += nv;
    }
    if (lane == 31) wsum[wrp] = ts;
    __syncthreads();
    if (tid == 0) {
        float a = 0.f;
#pragma unroll
        for (int i = 0; i < 8; i++) { float x = wsum[i]; wsum[i] = a; a += x; }
        wsum[8] = a;
    }
    __syncthreads();
    float base = wsum[wrp] + ts - s3;
    pd[tid * 4 + 0] = base + s0;
    pd[tid * 4 + 1] = base + s1;
    pd[tid * 4 + 2] = base + s2;
    pd[tid * 4 + 3] = base + s3;
    const float S = wsum[8];
    __syncthreads();

    const int n0 = wrp, n1 = wrp + 8;
    const float An0 = -__expf(A_log[d * NS + n0]);
    const float An1 = -__expf(A_log[d * NS + n1]);
    const float* B0p = g_bcT + ((size_t)b * 2 * NS + n0) * LL;
    const float* C0p = g_bcT + ((size_t)b * 2 * NS + NS + n0) * LL;
    const float* B1p = g_bcT + ((size_t)b * 2 * NS + n1) * LL;
    const float* C1p = g_bcT + ((size_t)b * 2 * NS + NS + n1) * LL;
    float carry0 = 0.f, carry1 = 0.f;

#pragma unroll
    for (int j = 0; j < 8; j++) {
        const int t = j * 128 + lane * 4;
        float dv[4], pv[4], b0[4], c0[4], b1[4], c1[4];
        *(float4*)dv = *(const float4*)&du[t];
        *(float4*)pv = *(const float4*)&pd[t];
        *(float4*)b0 = *(const float4*)&B0p[t];
        *(float4*)c0 = *(const float4*)&C0p[t];
        *(float4*)b1 = *(const float4*)&B1p[t];
        *(float4*)c1 = *(const float4*)&C1p[t];

        float e0[4], e1[4], p0[4], p1[4];
#pragma unroll
        for (int q = 0; q < 4; q++) {
            e0[q] = __expf(An0 * (S - pv[q]));
            e1[q] = __expf(An1 * (S - pv[q]));
            float z0 = dv[q] * b0[q] * e0[q];
            float z1 = dv[q] * b1[q] * e1[q];
            p0[q] = q ? (p0[q - 1] + z0) : z0;
            p1[q] = q ? (p1[q - 1] + z1) : z1;
        }
        float t0 = p0[3], t1 = p1[3];
#pragma unroll
        for (int o = 1; o < 32; o <<= 1) {
            float a0 = __shfl_up_sync(0xffffffffu, t0, o);
            float a1 = __shfl_up_sync(0xffffffffu, t1, o);
            if (lane >= o) { t0 += a0; t1 += a1; }
        }
        const float bs0 = carry0 + t0 - p0[3];
        const float bs1 = carry1 + t1 - p1[3];
        carry0 += __shfl_sync(0xffffffffu, t0, 31);
        carry1 += __shfl_sync(0xffffffffu, t1, 31);

        float acc4[4];
#pragma unroll
        for (int q = 0; q < 4; q++) {
            float x0 = (bs0 + p0[q]) / (e0[q] + 1e-12f);
            float x1 = (bs1 + p1[q]) / (e1[q] + 1e-12f);
            acc4[q] = x0 * c0[q] + x1 * c1[q];
        }
        *(float4*)&ysw[wrp][t] = *(const float4*)acc4;
    }
    __syncthreads();

    float4 r = ((const float4*)ysw[0])[tid];
#pragma unroll
    for (int w = 1; w < 8; w++) {
        float4 q = ((const float4*)ysw[w])[tid];
        r.x += q.x; r.y += q.y; r.z += q.z; r.w += q.w;
    }
    ((float4*)(g_yT + (size_t)bd * LL))[tid] = r;
}

// ---------------------------------------------------------------------------
// Transpose back + gate + bf16 split of y
// ---------------------------------------------------------------------------
__global__ __launch_bounds__(256)
void back_gate_kernel(const float* __restrict__ D_param) {
    __shared__ float tl[32][33];
    const int r0 = blockIdx.x * 32, d0 = blockIdx.y * 32;
    const int b = r0 / LL, tb = r0 % LL;
#pragma unroll
    for (int j = 0; j < 4; j++) {
        int d = d0 + threadIdx.y + j * 8;
        tl[threadIdx.y + j * 8][threadIdx.x] =
            g_yT[((size_t)b * DM + d) * LL + tb + threadIdx.x];
    }
    __syncthreads();
#pragma unroll
    for (int j = 0; j < 4; j++) {
        int row = r0 + threadIdx.y + j * 8;
        int d = d0 + threadIdx.x;
        float v = tl[threadIdx.x][threadIdx.y + j * 8];
        float uu = g_u[(size_t)row * DM + d];
        float sr = g_sres[(size_t)row * DM + d];
        float y = (v + uu * D_param[d]) * sr;
        __nv_bfloat16 h, l;
        split_bf16(y, h, l);
        g_yhi[(size_t)row * DM + d] = h;
        g_ylo[(size_t)row * DM + d] = l;
    }
}

// ---------------------------------------------------------------------------
extern "C" void kernel_launch(void* const* d_in, const int* in_sizes, int n_in,
                              void* d_out, int out_size) {
    const float* x       = (const float*)d_in[0];
    const float* W_in    = (const float*)d_in[1];
    const float* conv_w  = (const float*)d_in[2];
    const float* conv_b  = (const float*)d_in[3];
    const float* W_x     = (const float*)d_in[4];
    const float* W_delta = (const float*)d_in[5];
    const float* b_delta = (const float*)d_in[6];
    const float* A_log   = (const float*)d_in[7];
    const float* D_param = (const float*)d_in[8];
    const float* W_out   = (const float*)d_in[9];
    float* out = (float*)d_out;

    cudaFuncSetAttribute(hgemm<1>, cudaFuncAttributeMaxDynamicSharedMemorySize, HG_SMEM);
    cudaFuncSetAttribute(hgemm<2>, cudaFuncAttributeMaxDynamicSharedMemorySize, HG_SMEM);
    cudaFuncSetAttribute(hgemm<4>, cudaFuncAttributeMaxDynamicSharedMemorySize, HG_SMEM);

    float *p_xpp, *p_pout;
    cudaGetSymbolAddress((void**)&p_xpp,  g_xpp);
    cudaGetSymbolAddress((void**)&p_pout, g_pout);
    __nv_bfloat16 *p_xhi, *p_xlo, *p_uhi, *p_ulo, *p_yhi, *p_ylo, *p_xphi, *p_xplo;
    __nv_bfloat16 *p_wihi, *p_wilo, *p_wohi, *p_wolo, *p_wxhi, *p_wxlo, *p_wdhi, *p_wdlo;
    cudaGetSymbolAddress((void**)&p_xhi, g_xhi);
    cudaGetSymbolAddress((void**)&p_xlo, g_xlo);
    cudaGetSymbolAddress((void**)&p_uhi, g_uhi);
    cudaGetSymbolAddress((void**)&p_ulo, g_ulo);
    cudaGetSymbolAddress((void**)&p_yhi, g_yhi);
    cudaGetSymbolAddress((void**)&p_ylo, g_ylo);
    cudaGetSymbolAddress((void**)&p_xphi, g_xphi);
    cudaGetSymbolAddress((void**)&p_xplo, g_xplo);
    cudaGetSymbolAddress((void**)&p_wihi, g_wihi);
    cudaGetSymbolAddress((void**)&p_wilo, g_wilo);
    cudaGetSymbolAddress((void**)&p_wohi, g_wohi);
    cudaGetSymbolAddress((void**)&p_wolo, g_wolo);
    cudaGetSymbolAddress((void**)&p_wxhi, g_wxhi);
    cudaGetSymbolAddress((void**)&p_wxlo, g_wxlo);
    cudaGetSymbolAddress((void**)&p_wdhi, g_wdhi);
    cudaGetSymbolAddress((void**)&p_wdlo, g_wdlo);

    // 0) all prep in one launch
    prep_all_kernel<<<PREP_BLKS, 256>>>(x, W_in, W_out, W_x, W_delta);
    // 1) gemm1: x @ W_in -> xs0 | silu(res)
    hgemm<1><<<dim3(ML / 128, (2 * DM) / 64), 256, HG_SMEM>>>(
        p_xhi, p_xlo, p_wihi, p_wilo, nullptr, nullptr, 2 * DM, DM, 0);
    // 2) conv + silu -> u (+ split)
    conv_silu_kernel<<<(ML * DM + 255) / 256, 256>>>(conv_w, conv_b);
    // 3) gemm_x split-K=8: u @ W_x -> partials
    hgemm<4><<<dim3(ML / 128, 2, XSPL), 256, HG_SMEM>>>(
        p_uhi, p_ulo, p_wxhi, p_wxlo, p_xpp, nullptr, XPW, DM, DM / XSPL);
    // 3b) reduce partials -> xphi/xplo + bcT
    reduce_xp_kernel<<<(ML * XPW) / 256, 256>>>();
    // 4) delta gemm (fused transpose epilogue -> deltaT, duT)
    hgemm<2><<<dim3(ML / 128, DM / 64), 256, HG_SMEM>>>(
        p_xphi, p_xplo, p_wdhi, p_wdlo, nullptr, b_delta, DM, 64, 0);
    // 5) scan, gate
    scan_par_kernel<<<BB * DM, 256>>>(A_log);
    back_gate_kernel<<<dim3(ML / 32, DM / 32), dim3(32, 8)>>>(D_param);
    // 6) gemm_out split-K=2: y @ W_out -> partials, then reduce -> out
    hgemm<4><<<dim3(ML / 128, DM / 64, OSPL), 256, HG_SMEM>>>(
        p_yhi, p_ylo, p_wohi, p_wolo, p_pout, nullptr, DM, DM, DM / OSPL);
    reduce_out_kernel<<<(ML * DM / 4) / 256, 256>>>(out);
}